// round 5
// baseline (speedup 1.0000x reference)
#include <cuda_runtime.h>

#define T_STEPS 2048
#define BATCH   32
#define HID     256
#define INP     256

// Small scratch only (allocation-free rule: __device__ globals)
__device__ float g_WrT[HID * HID];   // W_rec transposed: [src][dst]
__device__ float g_WiT[INP * HID];   // W_in transposed:  [k][n]

// ---------------------------------------------------------------------------
// Transpose both weight matrices (tiny, one-time)
// ---------------------------------------------------------------------------
__global__ void transpose_weights(const float* __restrict__ Wi,
                                  const float* __restrict__ Wr) {
    int s = blockIdx.x;   // source (column) index
    int h = threadIdx.x;  // dest row index
    g_WiT[s * HID + h] = Wi[h * INP + s];
    g_WrT[s * HID + h] = Wr[h * HID + s];
}

// ---------------------------------------------------------------------------
// SGEMM: C[m,n] = sum_k A[m,k] * WiT[k,n]
// A = input reshaped (T*B, 256); C = xw buffer == d_out spike region (in-place
// reuse: lif_scan reads xw[t,b,h] before overwriting out[t,b,h]).
// 128x128 block tile, k-step 8, double-buffered smem, 8x8 per-thread microtile
// ---------------------------------------------------------------------------
__global__ __launch_bounds__(256) void sgemm_xw(const float* __restrict__ A,
                                                float* __restrict__ C) {
    __shared__ float As[2][8][128];
    __shared__ float Bs[2][8][128];

    const int tid = threadIdx.x;
    const int tx = tid & 15;        // 0..15 (n)
    const int ty = tid >> 4;        // 0..15 (m)
    const int bm = blockIdx.x * 128;
    const int bn = blockIdx.y * 128;

    const int arow = tid >> 1;          // 0..127
    const int acol = (tid & 1) * 4;     // 0 or 4
    const int brow = tid >> 5;          // 0..7
    const int bcol = (tid & 31) * 4;    // 0..124

    const float* Ap = A + (size_t)(bm + arow) * INP + acol;
    const float* Bp = g_WiT + brow * HID + bn + bcol;

    float4 a = *(const float4*)Ap;
    float4 b = *(const float4*)Bp;
    As[0][acol + 0][arow] = a.x;
    As[0][acol + 1][arow] = a.y;
    As[0][acol + 2][arow] = a.z;
    As[0][acol + 3][arow] = a.w;
    *(float4*)&Bs[0][brow][bcol] = b;
    __syncthreads();

    float acc[8][8];
#pragma unroll
    for (int i = 0; i < 8; ++i)
#pragma unroll
        for (int j = 0; j < 8; ++j) acc[i][j] = 0.0f;

    for (int kt = 0; kt < 32; ++kt) {
        const int cur = kt & 1;
        float4 an, bn4;
        if (kt < 31) {
            an  = *(const float4*)(Ap + (kt + 1) * 8);
            bn4 = *(const float4*)(Bp + (size_t)(kt + 1) * 8 * HID);
        }
#pragma unroll
        for (int k = 0; k < 8; ++k) {
            float4 a0 = *(const float4*)&As[cur][k][ty * 4];
            float4 a1 = *(const float4*)&As[cur][k][64 + ty * 4];
            float4 b0 = *(const float4*)&Bs[cur][k][tx * 4];
            float4 b1 = *(const float4*)&Bs[cur][k][64 + tx * 4];
            float av[8] = {a0.x, a0.y, a0.z, a0.w, a1.x, a1.y, a1.z, a1.w};
            float bv[8] = {b0.x, b0.y, b0.z, b0.w, b1.x, b1.y, b1.z, b1.w};
#pragma unroll
            for (int i = 0; i < 8; ++i)
#pragma unroll
                for (int j = 0; j < 8; ++j)
                    acc[i][j] = fmaf(av[i], bv[j], acc[i][j]);
        }
        if (kt < 31) {
            const int nxt = cur ^ 1;
            As[nxt][acol + 0][arow] = an.x;
            As[nxt][acol + 1][arow] = an.y;
            As[nxt][acol + 2][arow] = an.z;
            As[nxt][acol + 3][arow] = an.w;
            *(float4*)&Bs[nxt][brow][bcol] = bn4;
        }
        __syncthreads();
    }

#pragma unroll
    for (int i = 0; i < 8; ++i) {
        const int row = bm + ((i < 4) ? (ty * 4 + i) : (64 + ty * 4 + (i - 4)));
        float4 c0 = {acc[i][0], acc[i][1], acc[i][2], acc[i][3]};
        float4 c1 = {acc[i][4], acc[i][5], acc[i][6], acc[i][7]};
        *(float4*)&C[(size_t)row * HID + bn + tx * 4]      = c0;
        *(float4*)&C[(size_t)row * HID + bn + 64 + tx * 4] = c1;
    }
}

// ---------------------------------------------------------------------------
// LIF scan: one block per batch element, 256 threads.
// State/update: thread = hidden unit h.
// Recurrent gather: vectorized LDG.128 — 4 groups x 64 threads; group g
// processes spikes j == g (mod 4), each thread loads float4 (4 h-columns).
// Partials combined through shared memory. Spike list is per-warp compacted
// segments (no cross-warp prefix needed) -> 2 barriers/step.
// ---------------------------------------------------------------------------
__global__ __launch_bounds__(256) void lif_scan(
    const float* __restrict__ z0, const float* __restrict__ v0,
    const float* __restrict__ i0,
    float* __restrict__ out, float* __restrict__ zf,
    float* __restrict__ vf, float* __restrict__ sf)
{
    const int b    = blockIdx.x;
    const int h    = threadIdx.x;
    const int lane = h & 31;
    const int wid  = h >> 5;
    const int g    = h >> 6;     // gather group 0..3
    const int hq   = h & 63;     // float4 column index (covers h = 4*hq..4*hq+3)

    __shared__ unsigned short slist[8][32];   // per-warp compacted spike ids
    __shared__ int            counts[8];
    __shared__ float          partial[4][HID]; // 4KB group partials

    float v   = v0[b * HID + h];
    float syn = i0[b * HID + h];
    float z   = z0[b * HID + h];

    float* xop = out + b * HID + h;            // xw in, spikes out (in place)
    const float4* wr4 = (const float4*)g_WrT;  // row s: wr4[s*64 + hq]

    float xw_next = xop[0];

    for (int t = 0; t < T_STEPS; ++t) {
        // publish per-warp compacted spike segment + count
        const unsigned m = __ballot_sync(0xffffffffu, z > 0.0f);
        if (z > 0.0f)
            slist[wid][__popc(m & ((1u << lane) - 1u))] = (unsigned short)h;
        if (lane == 0) counts[wid] = __popc(m);

        const float xw_cur = xw_next;
        if (t + 1 < T_STEPS)
            xw_next = xop[(size_t)(t + 1) * (BATCH * HID)];  // prefetch 1 step ahead

        __syncthreads();   // slist/counts ready

        // vectorized sparse gather: group g takes spikes j%4==g of each segment
        float rx = 0.0f, ry = 0.0f, rz = 0.0f, rw = 0.0f;
        int c0 = counts[0], c1 = counts[1], c2 = counts[2], c3 = counts[3];
        int c4 = counts[4], c5 = counts[5], c6 = counts[6], c7 = counts[7];
        int cc[8] = {c0, c1, c2, c3, c4, c5, c6, c7};
#pragma unroll
        for (int w = 0; w < 8; ++w) {
            const int cw = cc[w];
            int j = g;
            for (; j + 4 < cw; j += 8) {
                const int sa = slist[w][j];
                const int sb = slist[w][j + 4];
                const float4 xa = __ldg(&wr4[sa * 64 + hq]);
                const float4 xb = __ldg(&wr4[sb * 64 + hq]);
                rx += xa.x; ry += xa.y; rz += xa.z; rw += xa.w;
                rx += xb.x; ry += xb.y; rz += xb.z; rw += xb.w;
            }
            if (j < cw) {
                const int sa = slist[w][j];
                const float4 xa = __ldg(&wr4[sa * 64 + hq]);
                rx += xa.x; ry += xa.y; rz += xa.z; rw += xa.w;
            }
        }
        float4 r4 = {rx, ry, rz, rw};
        *(float4*)&partial[g][hq * 4] = r4;

        __syncthreads();   // partials ready

        const float rec = (partial[0][h] + partial[1][h]) +
                          (partial[2][h] + partial[3][h]);

        // LIF update (match reference op order; no FMA contraction)
        const float vdec = __fadd_rn(v, __fmul_rn(0.1f, __fadd_rn(__fsub_rn(0.0f, v), syn)));
        const float idec = __fsub_rn(syn, __fmul_rn(0.2f, syn));
        const float zn   = (vdec - 1.0f > 0.0f) ? 1.0f : 0.0f;
        v   = (zn > 0.0f) ? 0.0f : vdec;
        syn = __fadd_rn(__fadd_rn(idec, xw_cur), rec);

        xop[(size_t)t * (BATCH * HID)] = zn;   // overwrite xw with spike
        z = zn;
    }

    zf[b * HID + h] = z;
    vf[b * HID + h] = v;
    sf[b * HID + h] = syn;
}

// ---------------------------------------------------------------------------
extern "C" void kernel_launch(void* const* d_in, const int* in_sizes, int n_in,
                              void* d_out, int out_size) {
    const float* input = (const float*)d_in[0];  // (T, B, IN)
    const float* z0    = (const float*)d_in[1];  // (B, H)
    const float* v0    = (const float*)d_in[2];
    const float* i0    = (const float*)d_in[3];
    const float* Wi    = (const float*)d_in[4];  // (H, IN)
    const float* Wr    = (const float*)d_in[5];  // (H, H)

    float* out = (float*)d_out;                         // (T, B, H) spikes
    float* zf  = out + (size_t)T_STEPS * BATCH * HID;   // (B, H)
    float* vf  = zf + BATCH * HID;
    float* sf  = vf + BATCH * HID;

    transpose_weights<<<HID, HID>>>(Wi, Wr);
    sgemm_xw<<<dim3((T_STEPS * BATCH) / 128, HID / 128), 256>>>(input, out);
    lif_scan<<<BATCH, HID>>>(z0, v0, i0, out, zf, vf, sf);
}